// round 7
// baseline (speedup 1.0000x reference)
#include <cuda_runtime.h>
#include <cstdint>

#define GXD 512
#define GYD 512
#define BBD 2
#define TTD 5
#define CCD 64
#define NSEG (BBD*TTD*GYD*GXD)   /* 2,621,440 */
#define PPD  (GYD*GXD)           /* 262,144  */

// ---------------- scratch (static __device__ — no allocations) ----------------
__device__ __align__(16) float  g_counts[NSEG];
__device__ __align__(16) float  g_sums[NSEG*3];
__device__ __align__(16) float  g_canvas[(size_t)NSEG*CCD];   // only rows with cnt>=2 are zeroed
__device__             double g_acc[55];     // [0..8] fsum, [9..53] fmom (upper tri), [54] nvalid
__device__ __align__(16) float  g_Ws[9*CCD]; // W folded with gamma*rstd
__device__ __align__(16) float  g_bias[CCD]; // beta - mu*scale

// ---------------- helpers ----------------
// XLA algebraic simplifier rewrites (x - pcr)/vox into (x - pcr) * (1/vox);
// 1/0.2f rounds to exactly 5.0f. Replicate: add.rn then mul.rn by 5.0f.
__device__ __forceinline__ bool compute_cell(const float* __restrict__ pt,
                                             int& seg, float& x, float& y, float& z,
                                             int& cx, int& cy) {
    float b = pt[0]; x = pt[1]; y = pt[2]; z = pt[3]; float t = pt[5];
    float cfx = __fmul_rn(__fadd_rn(x, 51.2f), 5.0f);
    float cfy = __fmul_rn(__fadd_rn(y, 51.2f), 5.0f);
    bool valid = (cfx >= 0.f) && (cfx < (float)GXD) && (cfy >= 0.f) && (cfy < (float)GYD);
    cx = (int)cfx; cx = cx < 0 ? 0 : (cx > GXD-1 ? GXD-1 : cx);
    cy = (int)cfy; cy = cy < 0 ? 0 : (cy > GYD-1 ? GYD-1 : cy);
    int bi = (int)b, ti = (int)t;
    seg = ((bi*TTD + ti)*GYD + cy)*GXD + cx;
    return valid;
}

__device__ __forceinline__ float warpsum(float v) {
    v += __shfl_down_sync(0xffffffffu, v, 16);
    v += __shfl_down_sync(0xffffffffu, v, 8);
    v += __shfl_down_sync(0xffffffffu, v, 4);
    v += __shfl_down_sync(0xffffffffu, v, 2);
    v += __shfl_down_sync(0xffffffffu, v, 1);
    return v;
}

__device__ __forceinline__ void build_feats(float* f, float x, float y, float z,
                                            float inten, int seg, int cx, int cy) {
    float cnt = g_counts[seg];
    float d   = fmaxf(cnt, 1.0f);
    float mx  = __fdiv_rn(g_sums[seg*3+0], d);
    float my  = __fdiv_rn(g_sums[seg*3+1], d);
    float mz  = __fdiv_rn(g_sums[seg*3+2], d);
    float cenx = __fadd_rn(__fadd_rn(__fmul_rn((float)cx, 0.2f), 0.1f), -51.2f);
    float ceny = __fadd_rn(__fadd_rn(__fmul_rn((float)cy, 0.2f), 0.1f), -51.2f);
    f[0] = x; f[1] = y; f[2] = z; f[3] = inten;
    f[4] = x - mx; f[5] = y - my; f[6] = z - mz;
    f[7] = x - cenx; f[8] = y - ceny;
}

// ---------------- pass 1: per-pillar count + xyz sums, nvalid ----------------
__global__ void pass1(const float* __restrict__ pts, int n) {
    int i = blockIdx.x*blockDim.x + threadIdx.x;
    bool valid = false; int seg = 0, cx, cy; float x = 0.f, y = 0.f, z = 0.f;
    if (i < n) valid = compute_cell(pts + (size_t)i*6, seg, x, y, z, cx, cy);
    if (valid) {
        atomicAdd(&g_counts[seg], 1.0f);
        atomicAdd(&g_sums[seg*3+0], x);
        atomicAdd(&g_sums[seg*3+1], y);
        atomicAdd(&g_sums[seg*3+2], z);
    }
    unsigned m = __ballot_sync(0xffffffffu, valid);
    if ((threadIdx.x & 31) == 0 && m)
        atomicAdd(&g_acc[54], (double)__popc(m));
}

// -------- zero canvas rows only where cnt >= 2 (atomicMax baseline needed) ----
__global__ void zero_multi(int nseg) {
    int i = blockIdx.x*blockDim.x + threadIdx.x;
    if (i >= nseg) return;
    if (g_counts[i] >= 2.0f) {
        float4* p = (float4*)&g_canvas[(size_t)i*CCD];
        float4 zz = make_float4(0.f,0.f,0.f,0.f);
        #pragma unroll
        for (int k = 0; k < 16; k++) p[k] = zz;
    }
}

// ---------------- pass 2: feat first + second moments (for folded BN) --------
__global__ void pass2(const float* __restrict__ pts, int n) {
    __shared__ double sacc[54];
    int tid = threadIdx.x;
    if (tid < 54) sacc[tid] = 0.0;
    __syncthreads();

    int i = blockIdx.x*blockDim.x + tid;
    float f[9];
    #pragma unroll
    for (int k = 0; k < 9; k++) f[k] = 0.f;
    if (i < n) {
        int seg, cx, cy; float x, y, z;
        bool valid = compute_cell(pts + (size_t)i*6, seg, x, y, z, cx, cy);
        if (valid) {
            float inten = pts[(size_t)i*6 + 4];
            build_feats(f, x, y, z, inten, seg, cx, cy);
        }
    }
    bool lane0 = ((tid & 31) == 0);
    int k = 0;
    #pragma unroll
    for (int a = 0; a < 9; a++, k++) {
        float v = warpsum(f[a]);
        if (lane0) atomicAdd(&sacc[k], (double)v);
    }
    #pragma unroll
    for (int a = 0; a < 9; a++) {
        #pragma unroll
        for (int b2 = a; b2 < 9; b2++, k++) {
            float v = warpsum(f[a]*f[b2]);
            if (lane0) atomicAdd(&sacc[k], (double)v);
        }
    }
    __syncthreads();
    if (tid < 54) {
        double v = sacc[tid];
        if (v != 0.0) atomicAdd(&g_acc[tid], v);
    }
}

// ---------------- finalize: fold BN into W/bias ----------------
__global__ void finalize_bn(const float* __restrict__ W,
                            const float* __restrict__ gamma,
                            const float* __restrict__ beta) {
    int c = threadIdx.x;   // 64 threads
    double nv = g_acc[54]; if (nv < 1.0) nv = 1.0;
    float w[9];
    #pragma unroll
    for (int r = 0; r < 9; r++) w[r] = W[r*CCD + c];
    double mu = 0.0;
    #pragma unroll
    for (int r = 0; r < 9; r++) mu += g_acc[r] * (double)w[r];
    mu /= nv;
    double ex2 = 0.0; int k = 9;
    #pragma unroll
    for (int a = 0; a < 9; a++) {
        #pragma unroll
        for (int b2 = a; b2 < 9; b2++, k++) {
            double contrib = g_acc[k] * (double)w[a] * (double)w[b2];
            if (a != b2) contrib *= 2.0;
            ex2 += contrib;
        }
    }
    ex2 /= nv;
    double var = ex2 - mu*mu;
    float rstd = rsqrtf((float)var + 1e-3f);
    float sc = gamma[c] * rstd;
    float bi = beta[c] - (float)mu * sc;
    #pragma unroll
    for (int r = 0; r < 9; r++) g_Ws[r*CCD + c] = w[r] * sc;
    g_bias[c] = bi;
}

// ---------------- pass 3: matvec + relu + scatter-max into canvas ------------
__global__ void pass3(const float* __restrict__ pts, int n) {
    __shared__ float4 sW[9*16];   // [r][c4]
    __shared__ float4 sB[16];
    int tid = threadIdx.x;
    if (tid < 144) sW[tid] = ((const float4*)g_Ws)[tid];
    if (tid < 16)  sB[tid] = ((const float4*)g_bias)[tid];
    __syncthreads();

    int i = blockIdx.x*blockDim.x + tid;
    if (i >= n) return;
    int seg, cx, cy; float x, y, z;
    bool valid = compute_cell(pts + (size_t)i*6, seg, x, y, z, cx, cy);
    if (!valid) return;
    float inten = pts[(size_t)i*6 + 4];
    float f[9];
    build_feats(f, x, y, z, inten, seg, cx, cy);

    float cnt = g_counts[seg];
    float* base = &g_canvas[(size_t)seg * CCD];
    bool single = (cnt == 1.0f);

    #pragma unroll
    for (int c4 = 0; c4 < 16; c4++) {
        float4 acc = sB[c4];
        #pragma unroll
        for (int r = 0; r < 9; r++) {
            float4 wv = sW[r*16 + c4];
            acc.x = fmaf(f[r], wv.x, acc.x);
            acc.y = fmaf(f[r], wv.y, acc.y);
            acc.z = fmaf(f[r], wv.z, acc.z);
            acc.w = fmaf(f[r], wv.w, acc.w);
        }
        acc.x = fmaxf(acc.x, 0.f); acc.y = fmaxf(acc.y, 0.f);
        acc.z = fmaxf(acc.z, 0.f); acc.w = fmaxf(acc.w, 0.f);
        if (single) {
            ((float4*)base)[c4] = acc;   // sole writer of this pillar
        } else {
            atomicMax((int*)(base + c4*4 + 0), __float_as_int(acc.x));
            atomicMax((int*)(base + c4*4 + 1), __float_as_int(acc.y));
            atomicMax((int*)(base + c4*4 + 2), __float_as_int(acc.z));
            atomicMax((int*)(base + c4*4 + 3), __float_as_int(acc.w));
        }
    }
}

// ---------------- transpose: [B,T,GY,GX,C] -> [B,C,T,GY,GX], mask cnt==0 ------
__global__ void transpose_k(float* __restrict__ out) {
    __shared__ float tile[64][65];
    __shared__ float scnt[64];
    int bt = blockIdx.y;                 // 0..9
    int p0 = blockIdx.x * 64;            // pillar base within one (b,t) plane
    int b  = bt / TTD, t = bt % TTD;
    int tid = threadIdx.x;               // 256 threads

    if (tid < 64) scnt[tid] = g_counts[(size_t)bt * PPD + p0 + tid];

    const float* src = g_canvas + ((size_t)bt * PPD + p0) * CCD;
    #pragma unroll
    for (int it = 0; it < 4; it++) {
        int row = it*16 + (tid >> 4);
        int v   = tid & 15;
        float4 d = *(const float4*)(src + (size_t)row*CCD + v*4);
        tile[row][v*4+0] = d.x; tile[row][v*4+1] = d.y;
        tile[row][v*4+2] = d.z; tile[row][v*4+3] = d.w;
    }
    __syncthreads();
    #pragma unroll
    for (int it = 0; it < 16; it++) {
        int c  = it*4 + (tid >> 6);
        int pl = tid & 63;
        float v = (scnt[pl] > 0.0f) ? tile[pl][c] : 0.0f;
        out[(((size_t)(b*CCD + c))*TTD + t)*PPD + p0 + pl] = v;
    }
}

// ---------------- launch ----------------
extern "C" void kernel_launch(void* const* d_in, const int* in_sizes, int n_in,
                              void* d_out, int out_size) {
    const float* pts   = (const float*)d_in[0];
    const float* W     = (const float*)d_in[1];
    const float* gamma = (const float*)d_in[2];
    const float* beta  = (const float*)d_in[3];
    float* out = (float*)d_out;
    int n = in_sizes[0] / 6;

    void *pc, *ps, *pa;
    cudaGetSymbolAddress(&pc, g_counts);
    cudaGetSymbolAddress(&ps, g_sums);
    cudaGetSymbolAddress(&pa, g_acc);
    cudaMemsetAsync(pc, 0, sizeof(float)*NSEG);
    cudaMemsetAsync(ps, 0, sizeof(float)*NSEG*3);
    cudaMemsetAsync(pa, 0, 55*sizeof(double));

    int nb = (n + 255) / 256;
    pass1<<<nb, 256>>>(pts, n);
    zero_multi<<<(NSEG + 255)/256, 256>>>(NSEG);
    pass2<<<nb, 256>>>(pts, n);
    finalize_bn<<<1, 64>>>(W, gamma, beta);
    pass3<<<nb, 256>>>(pts, n);
    dim3 tg(PPD/64, BBD*TTD);
    transpose_k<<<tg, 256>>>(out);
}

// round 8
// speedup vs baseline: 1.2149x; 1.2149x over previous
#include <cuda_runtime.h>
#include <cstdint>

#define GXD 512
#define GYD 512
#define BBD 2
#define TTD 5
#define CCD 64
#define NSEG (BBD*TTD*GYD*GXD)   /* 2,621,440 */
#define PPD  (GYD*GXD)           /* 262,144  */

// ---------------- scratch (static __device__ — no allocations) ----------------
__device__ __align__(16) float        g_counts[NSEG];
__device__ __align__(16) float        g_sums[NSEG*3];
__device__ __align__(16) unsigned int g_canvas[(size_t)NSEG*CCD]; // order-preserving keys of RAW scores
__device__             double       g_acc[55];   // [0..8] fsum, [9..53] fmom (upper tri), [54] nvalid
__device__ __align__(16) float        g_scale[CCD]; // gamma * rstd
__device__ __align__(16) float        g_bias2[CCD]; // beta - mu*scale

// ---------------- helpers ----------------
// XLA algebraic simplifier rewrites (x - pcr)/vox into (x - pcr) * (1/vox);
// 1/0.2f rounds to exactly 5.0f. Replicate: add.rn then mul.rn by 5.0f.
__device__ __forceinline__ bool compute_cell(const float* __restrict__ pt,
                                             int& seg, float& x, float& y, float& z,
                                             int& cx, int& cy) {
    float b = pt[0]; x = pt[1]; y = pt[2]; z = pt[3]; float t = pt[5];
    float cfx = __fmul_rn(__fadd_rn(x, 51.2f), 5.0f);
    float cfy = __fmul_rn(__fadd_rn(y, 51.2f), 5.0f);
    bool valid = (cfx >= 0.f) && (cfx < (float)GXD) && (cfy >= 0.f) && (cfy < (float)GYD);
    cx = (int)cfx; cx = cx < 0 ? 0 : (cx > GXD-1 ? GXD-1 : cx);
    cy = (int)cfy; cy = cy < 0 ? 0 : (cy > GYD-1 ? GYD-1 : cy);
    int bi = (int)b, ti = (int)t;
    seg = ((bi*TTD + ti)*GYD + cy)*GXD + cx;
    return valid;
}

__device__ __forceinline__ float warpsum(float v) {
    v += __shfl_down_sync(0xffffffffu, v, 16);
    v += __shfl_down_sync(0xffffffffu, v, 8);
    v += __shfl_down_sync(0xffffffffu, v, 4);
    v += __shfl_down_sync(0xffffffffu, v, 2);
    v += __shfl_down_sync(0xffffffffu, v, 1);
    return v;
}

__device__ __forceinline__ void build_feats(float* f, float x, float y, float z,
                                            float inten, int seg, int cx, int cy) {
    float cnt = g_counts[seg];
    float d   = fmaxf(cnt, 1.0f);
    float mx  = __fdiv_rn(g_sums[seg*3+0], d);
    float my  = __fdiv_rn(g_sums[seg*3+1], d);
    float mz  = __fdiv_rn(g_sums[seg*3+2], d);
    float cenx = __fadd_rn(__fadd_rn(__fmul_rn((float)cx, 0.2f), 0.1f), -51.2f);
    float ceny = __fadd_rn(__fadd_rn(__fmul_rn((float)cy, 0.2f), 0.1f), -51.2f);
    f[0] = x; f[1] = y; f[2] = z; f[3] = inten;
    f[4] = x - mx; f[5] = y - my; f[6] = z - mz;
    f[7] = x - cenx; f[8] = y - ceny;
}

// order-preserving float<->uint key (works for negative raw scores)
__device__ __forceinline__ unsigned enc_key(float f) {
    int i = __float_as_int(f);
    return (i >= 0) ? ((unsigned)i | 0x80000000u) : ~(unsigned)i;
}
__device__ __forceinline__ float dec_key(unsigned k) {
    int i = (k & 0x80000000u) ? (int)(k & 0x7FFFFFFFu) : (int)(~k);
    return __int_as_float(i);
}

// ---------------- pass 1: per-pillar count + xyz sums, nvalid ----------------
__global__ void pass1(const float* __restrict__ pts, int n) {
    int i = blockIdx.x*blockDim.x + threadIdx.x;
    bool valid = false; int seg = 0, cx, cy; float x = 0.f, y = 0.f, z = 0.f;
    if (i < n) valid = compute_cell(pts + (size_t)i*6, seg, x, y, z, cx, cy);
    if (valid) {
        atomicAdd(&g_counts[seg], 1.0f);
        atomicAdd(&g_sums[seg*3+0], x);
        atomicAdd(&g_sums[seg*3+1], y);
        atomicAdd(&g_sums[seg*3+2], z);
    }
    unsigned m = __ballot_sync(0xffffffffu, valid);
    if ((threadIdx.x & 31) == 0 && m)
        atomicAdd(&g_acc[54], (double)__popc(m));
}

// -------- zero canvas rows only where cnt >= 2 (atomicMax baseline = key 0) ---
__global__ void zero_multi(int nseg) {
    int i = blockIdx.x*blockDim.x + threadIdx.x;
    if (i >= nseg) return;
    if (g_counts[i] >= 2.0f) {
        uint4* p = (uint4*)&g_canvas[(size_t)i*CCD];
        uint4 zz = make_uint4(0u,0u,0u,0u);
        #pragma unroll
        for (int k = 0; k < 16; k++) p[k] = zz;
    }
}

// ------- fused pass: moments (register-accumulated) + raw matvec scatter-max --
__global__ void __launch_bounds__(256) pass23(const float* __restrict__ pts, int n,
                                              const float* __restrict__ W) {
    __shared__ float4 sW[9*16];   // raw W [r][c4]
    __shared__ double sacc[54];
    int tid = threadIdx.x;
    if (tid < 144) sW[tid] = ((const float4*)W)[tid];
    if (tid < 54)  sacc[tid] = 0.0;
    __syncthreads();

    float m[54];
    #pragma unroll
    for (int k = 0; k < 54; k++) m[k] = 0.f;

    int stride = gridDim.x * blockDim.x;
    for (int i = blockIdx.x*blockDim.x + tid; i < n; i += stride) {
        int seg, cx, cy; float x, y, z;
        bool valid = compute_cell(pts + (size_t)i*6, seg, x, y, z, cx, cy);
        if (!valid) continue;
        float inten = pts[(size_t)i*6 + 4];
        float f[9];
        build_feats(f, x, y, z, inten, seg, cx, cy);

        // moments in registers
        int k = 0;
        #pragma unroll
        for (int a = 0; a < 9; a++, k++) m[k] += f[a];
        #pragma unroll
        for (int a = 0; a < 9; a++)
            #pragma unroll
            for (int b2 = a; b2 < 9; b2++, k++) m[k] = fmaf(f[a], f[b2], m[k]);

        // raw matvec + scatter-max (keys)
        float cnt = g_counts[seg];
        unsigned* base = &g_canvas[(size_t)seg * CCD];
        bool single = (cnt == 1.0f);
        #pragma unroll
        for (int c4 = 0; c4 < 16; c4++) {
            float4 acc = make_float4(0.f,0.f,0.f,0.f);
            #pragma unroll
            for (int r = 0; r < 9; r++) {
                float4 wv = sW[r*16 + c4];
                acc.x = fmaf(f[r], wv.x, acc.x);
                acc.y = fmaf(f[r], wv.y, acc.y);
                acc.z = fmaf(f[r], wv.z, acc.z);
                acc.w = fmaf(f[r], wv.w, acc.w);
            }
            unsigned kx = enc_key(acc.x), ky = enc_key(acc.y);
            unsigned kz = enc_key(acc.z), kw = enc_key(acc.w);
            if (single) {
                ((uint4*)base)[c4] = make_uint4(kx, ky, kz, kw);
            } else {
                atomicMax(base + c4*4 + 0, kx);
                atomicMax(base + c4*4 + 1, ky);
                atomicMax(base + c4*4 + 2, kz);
                atomicMax(base + c4*4 + 3, kw);
            }
        }
    }

    // block-level moment reduction
    bool lane0 = ((tid & 31) == 0);
    #pragma unroll
    for (int k = 0; k < 54; k++) {
        float v = warpsum(m[k]);
        if (lane0 && v != 0.f) atomicAdd(&sacc[k], (double)v);
    }
    __syncthreads();
    if (tid < 54) {
        double v = sacc[tid];
        if (v != 0.0) atomicAdd(&g_acc[tid], v);
    }
}

// ---------------- finalize: BN scale/bias from moments ----------------
__global__ void finalize_bn(const float* __restrict__ W,
                            const float* __restrict__ gamma,
                            const float* __restrict__ beta) {
    int c = threadIdx.x;   // 64 threads
    double nv = g_acc[54]; if (nv < 1.0) nv = 1.0;
    float w[9];
    #pragma unroll
    for (int r = 0; r < 9; r++) w[r] = W[r*CCD + c];
    double mu = 0.0;
    #pragma unroll
    for (int r = 0; r < 9; r++) mu += g_acc[r] * (double)w[r];
    mu /= nv;
    double ex2 = 0.0; int k = 9;
    #pragma unroll
    for (int a = 0; a < 9; a++) {
        #pragma unroll
        for (int b2 = a; b2 < 9; b2++, k++) {
            double contrib = g_acc[k] * (double)w[a] * (double)w[b2];
            if (a != b2) contrib *= 2.0;
            ex2 += contrib;
        }
    }
    ex2 /= nv;
    double var = ex2 - mu*mu;
    float rstd = rsqrtf((float)var + 1e-3f);
    float sc = gamma[c] * rstd;
    g_scale[c] = sc;
    g_bias2[c] = beta[c] - (float)mu * sc;
}

// --- transpose + BN+relu: [B,T,GY,GX,C] -> [B,C,T,GY,GX], skip empty reads ----
__global__ void transpose_k(float* __restrict__ out) {
    __shared__ unsigned tile[64][65];
    __shared__ float scnt[64];
    __shared__ float ssc[CCD], sbi[CCD];
    int bt = blockIdx.y;                 // 0..9
    int p0 = blockIdx.x * 64;            // pillar base within one (b,t) plane
    int b  = bt / TTD, t = bt % TTD;
    int tid = threadIdx.x;               // 256 threads

    if (tid < 64)        scnt[tid] = g_counts[(size_t)bt * PPD + p0 + tid];
    else if (tid < 128)  ssc[tid-64] = g_scale[tid-64];
    else if (tid < 192)  sbi[tid-128] = g_bias2[tid-128];
    __syncthreads();

    const unsigned* src = g_canvas + ((size_t)bt * PPD + p0) * CCD;
    #pragma unroll
    for (int it = 0; it < 4; it++) {
        int row = it*16 + (tid >> 4);
        int v   = tid & 15;
        if (scnt[row] > 0.0f) {          // skip 256B read for empty pillars
            uint4 d = *(const uint4*)(src + (size_t)row*CCD + v*4);
            tile[row][v*4+0] = d.x; tile[row][v*4+1] = d.y;
            tile[row][v*4+2] = d.z; tile[row][v*4+3] = d.w;
        }
    }
    __syncthreads();
    #pragma unroll
    for (int it = 0; it < 16; it++) {
        int c  = it*4 + (tid >> 6);
        int pl = tid & 63;
        float v = 0.0f;
        if (scnt[pl] > 0.0f) {
            float s = dec_key(tile[pl][c]);
            v = fmaxf(fmaf(ssc[c], s, sbi[c]), 0.0f);
        }
        out[(((size_t)(b*CCD + c))*TTD + t)*PPD + p0 + pl] = v;
    }
}

// ---------------- launch ----------------
extern "C" void kernel_launch(void* const* d_in, const int* in_sizes, int n_in,
                              void* d_out, int out_size) {
    const float* pts   = (const float*)d_in[0];
    const float* W     = (const float*)d_in[1];
    const float* gamma = (const float*)d_in[2];
    const float* beta  = (const float*)d_in[3];
    float* out = (float*)d_out;
    int n = in_sizes[0] / 6;

    void *pc, *ps, *pa;
    cudaGetSymbolAddress(&pc, g_counts);
    cudaGetSymbolAddress(&ps, g_sums);
    cudaGetSymbolAddress(&pa, g_acc);
    cudaMemsetAsync(pc, 0, sizeof(float)*NSEG);
    cudaMemsetAsync(ps, 0, sizeof(float)*NSEG*3);
    cudaMemsetAsync(pa, 0, 55*sizeof(double));

    int nb = (n + 255) / 256;
    pass1<<<nb, 256>>>(pts, n);
    zero_multi<<<(NSEG + 255)/256, 256>>>(NSEG);
    pass23<<<296, 256>>>(pts, n, W);
    finalize_bn<<<1, 64>>>(W, gamma, beta);
    dim3 tg(PPD/64, BBD*TTD);
    transpose_k<<<tg, 256>>>(out);
}

// round 11
// speedup vs baseline: 1.2173x; 1.0020x over previous
#include <cuda_runtime.h>
#include <cstdint>

#define GXD 512
#define GYD 512
#define BBD 2
#define TTD 5
#define CCD 64
#define NSEG (BBD*TTD*GYD*GXD)   /* 2,621,440 */
#define PPD  (GYD*GXD)           /* 262,144  */
#define ACC_PAD 32               /* 32 float4 = 512B tail for g_acc (55 doubles = 440B) */

// ---------------- scratch (static __device__ — no allocations) ----------------
// g_pil[i] = (count, sum_x, sum_y, sum_z); tail [NSEG..NSEG+ACC_PAD) holds g_acc doubles
__device__ __align__(16) float4       g_pil[NSEG + ACC_PAD];
__device__ __align__(16) unsigned int g_canvas[(size_t)NSEG*CCD]; // order-preserving keys of RAW scores
__device__ __align__(16) float        g_scale[CCD]; // gamma * rstd
__device__ __align__(16) float        g_bias2[CCD]; // beta - mu*scale

__device__ __forceinline__ double* acc_ptr() { return (double*)&g_pil[NSEG]; }

// ---------------- helpers ----------------
// XLA algebraic simplifier rewrites (x - pcr)/vox into (x - pcr) * (1/vox);
// 1/0.2f rounds to exactly 5.0f. Replicate: add.rn then mul.rn by 5.0f.
__device__ __forceinline__ bool compute_cell(const float* __restrict__ pt,
                                             int& seg, float& x, float& y, float& z,
                                             int& cx, int& cy) {
    float b = pt[0]; x = pt[1]; y = pt[2]; z = pt[3]; float t = pt[5];
    float cfx = __fmul_rn(__fadd_rn(x, 51.2f), 5.0f);
    float cfy = __fmul_rn(__fadd_rn(y, 51.2f), 5.0f);
    bool valid = (cfx >= 0.f) && (cfx < (float)GXD) && (cfy >= 0.f) && (cfy < (float)GYD);
    cx = (int)cfx; cx = cx < 0 ? 0 : (cx > GXD-1 ? GXD-1 : cx);
    cy = (int)cfy; cy = cy < 0 ? 0 : (cy > GYD-1 ? GYD-1 : cy);
    int bi = (int)b, ti = (int)t;
    seg = ((bi*TTD + ti)*GYD + cy)*GXD + cx;
    return valid;
}

__device__ __forceinline__ float warpsum(float v) {
    v += __shfl_down_sync(0xffffffffu, v, 16);
    v += __shfl_down_sync(0xffffffffu, v, 8);
    v += __shfl_down_sync(0xffffffffu, v, 4);
    v += __shfl_down_sync(0xffffffffu, v, 2);
    v += __shfl_down_sync(0xffffffffu, v, 1);
    return v;
}

// one float4 gather replaces 4 scattered scalar loads
__device__ __forceinline__ float build_feats(float* f, float x, float y, float z,
                                             float inten, int seg, int cx, int cy) {
    float4 p = g_pil[seg];
    float cnt = p.x;
    float d   = fmaxf(cnt, 1.0f);
    float mx  = __fdiv_rn(p.y, d);
    float my  = __fdiv_rn(p.z, d);
    float mz  = __fdiv_rn(p.w, d);
    float cenx = __fadd_rn(__fadd_rn(__fmul_rn((float)cx, 0.2f), 0.1f), -51.2f);
    float ceny = __fadd_rn(__fadd_rn(__fmul_rn((float)cy, 0.2f), 0.1f), -51.2f);
    f[0] = x; f[1] = y; f[2] = z; f[3] = inten;
    f[4] = x - mx; f[5] = y - my; f[6] = z - mz;
    f[7] = x - cenx; f[8] = y - ceny;
    return cnt;
}

// order-preserving float<->uint key (works for negative raw scores)
__device__ __forceinline__ unsigned enc_key(float f) {
    int i = __float_as_int(f);
    return (i >= 0) ? ((unsigned)i | 0x80000000u) : ~(unsigned)i;
}
__device__ __forceinline__ float dec_key(unsigned k) {
    int i = (k & 0x80000000u) ? (int)(k & 0x7FFFFFFFu) : (int)(~k);
    return __int_as_float(i);
}

// ---------------- pass 1: per-pillar count + xyz sums, nvalid ----------------
__global__ void pass1(const float* __restrict__ pts, int n) {
    int i = blockIdx.x*blockDim.x + threadIdx.x;
    bool valid = false; int seg = 0, cx, cy; float x = 0.f, y = 0.f, z = 0.f;
    if (i < n) valid = compute_cell(pts + (size_t)i*6, seg, x, y, z, cx, cy);
    if (valid) {
        float* p = (float*)&g_pil[seg];   // 4 atomics into one 16B span (same line)
        atomicAdd(p + 0, 1.0f);
        atomicAdd(p + 1, x);
        atomicAdd(p + 2, y);
        atomicAdd(p + 3, z);
    }
    unsigned m = __ballot_sync(0xffffffffu, valid);
    if ((threadIdx.x & 31) == 0 && m)
        atomicAdd(&acc_ptr()[54], (double)__popc(m));
}

// -------- zero canvas rows only where cnt >= 2 (atomicMax baseline = key 0) ---
__global__ void zero_multi(int nseg) {
    int i = blockIdx.x*blockDim.x + threadIdx.x;
    if (i >= nseg) return;
    if (g_pil[i].x >= 2.0f) {
        uint4* p = (uint4*)&g_canvas[(size_t)i*CCD];
        uint4 zz = make_uint4(0u,0u,0u,0u);
        #pragma unroll
        for (int k = 0; k < 16; k++) p[k] = zz;
    }
}

// ------- fused pass: moments (register-accumulated) + raw matvec scatter-max --
__global__ void __launch_bounds__(256) pass23(const float* __restrict__ pts, int n,
                                              const float* __restrict__ W) {
    __shared__ float4 sW[9*16];   // raw W [r][c4]
    __shared__ double sacc[54];
    int tid = threadIdx.x;
    if (tid < 144) sW[tid] = ((const float4*)W)[tid];
    if (tid < 54)  sacc[tid] = 0.0;
    __syncthreads();

    float m[54];
    #pragma unroll
    for (int k = 0; k < 54; k++) m[k] = 0.f;

    int stride = gridDim.x * blockDim.x;
    for (int i = blockIdx.x*blockDim.x + tid; i < n; i += stride) {
        int seg, cx, cy; float x, y, z;
        bool valid = compute_cell(pts + (size_t)i*6, seg, x, y, z, cx, cy);
        if (!valid) continue;
        float inten = pts[(size_t)i*6 + 4];
        float f[9];
        float cnt = build_feats(f, x, y, z, inten, seg, cx, cy);

        // moments in registers
        int k = 0;
        #pragma unroll
        for (int a = 0; a < 9; a++, k++) m[k] += f[a];
        #pragma unroll
        for (int a = 0; a < 9; a++)
            #pragma unroll
            for (int b2 = a; b2 < 9; b2++, k++) m[k] = fmaf(f[a], f[b2], m[k]);

        // raw matvec + scatter-max (keys)
        unsigned* base = &g_canvas[(size_t)seg * CCD];
        bool single = (cnt == 1.0f);
        #pragma unroll
        for (int c4 = 0; c4 < 16; c4++) {
            float4 acc = make_float4(0.f,0.f,0.f,0.f);
            #pragma unroll
            for (int r = 0; r < 9; r++) {
                float4 wv = sW[r*16 + c4];
                acc.x = fmaf(f[r], wv.x, acc.x);
                acc.y = fmaf(f[r], wv.y, acc.y);
                acc.z = fmaf(f[r], wv.z, acc.z);
                acc.w = fmaf(f[r], wv.w, acc.w);
            }
            unsigned kx = enc_key(acc.x), ky = enc_key(acc.y);
            unsigned kz = enc_key(acc.z), kw = enc_key(acc.w);
            if (single) {
                ((uint4*)base)[c4] = make_uint4(kx, ky, kz, kw);
            } else {
                atomicMax(base + c4*4 + 0, kx);
                atomicMax(base + c4*4 + 1, ky);
                atomicMax(base + c4*4 + 2, kz);
                atomicMax(base + c4*4 + 3, kw);
            }
        }
    }

    // block-level moment reduction
    bool lane0 = ((tid & 31) == 0);
    #pragma unroll
    for (int k = 0; k < 54; k++) {
        float v = warpsum(m[k]);
        if (lane0 && v != 0.f) atomicAdd(&sacc[k], (double)v);
    }
    __syncthreads();
    if (tid < 54) {
        double v = sacc[tid];
        if (v != 0.0) atomicAdd(&acc_ptr()[tid], v);
    }
}

// ---------------- finalize: BN scale/bias from moments ----------------
__global__ void finalize_bn(const float* __restrict__ W,
                            const float* __restrict__ gamma,
                            const float* __restrict__ beta) {
    int c = threadIdx.x;   // 64 threads
    const double* ga = acc_ptr();
    double nv = ga[54]; if (nv < 1.0) nv = 1.0;
    float w[9];
    #pragma unroll
    for (int r = 0; r < 9; r++) w[r] = W[r*CCD + c];
    double mu = 0.0;
    #pragma unroll
    for (int r = 0; r < 9; r++) mu += ga[r] * (double)w[r];
    mu /= nv;
    double ex2 = 0.0; int k = 9;
    #pragma unroll
    for (int a = 0; a < 9; a++) {
        #pragma unroll
        for (int b2 = a; b2 < 9; b2++, k++) {
            double contrib = ga[k] * (double)w[a] * (double)w[b2];
            if (a != b2) contrib *= 2.0;
            ex2 += contrib;
        }
    }
    ex2 /= nv;
    double var = ex2 - mu*mu;
    float rstd = rsqrtf((float)var + 1e-3f);
    float sc = gamma[c] * rstd;
    g_scale[c] = sc;
    g_bias2[c] = beta[c] - (float)mu * sc;
}

// --- transpose + BN+relu: [B,T,GY,GX,C] -> [B,C,T,GY,GX], skip empty reads ----
__global__ void transpose_k(float* __restrict__ out) {
    __shared__ unsigned tile[64][65];
    __shared__ float scnt[64];
    __shared__ float ssc[CCD], sbi[CCD];
    int bt = blockIdx.y;                 // 0..9
    int p0 = blockIdx.x * 64;            // pillar base within one (b,t) plane
    int b  = bt / TTD, t = bt % TTD;
    int tid = threadIdx.x;               // 256 threads

    if (tid < 64)        scnt[tid] = g_pil[(size_t)bt * PPD + p0 + tid].x;
    else if (tid < 128)  ssc[tid-64] = g_scale[tid-64];
    else if (tid < 192)  sbi[tid-128] = g_bias2[tid-128];
    __syncthreads();

    const unsigned* src = g_canvas + ((size_t)bt * PPD + p0) * CCD;
    #pragma unroll
    for (int it = 0; it < 4; it++) {
        int row = it*16 + (tid >> 4);
        int v   = tid & 15;
        if (scnt[row] > 0.0f) {          // skip 256B read for empty pillars
            uint4 d = *(const uint4*)(src + (size_t)row*CCD + v*4);
            tile[row][v*4+0] = d.x; tile[row][v*4+1] = d.y;
            tile[row][v*4+2] = d.z; tile[row][v*4+3] = d.w;
        }
    }
    __syncthreads();
    #pragma unroll
    for (int it = 0; it < 16; it++) {
        int c  = it*4 + (tid >> 6);
        int pl = tid & 63;
        float v = 0.0f;
        if (scnt[pl] > 0.0f) {
            float s = dec_key(tile[pl][c]);
            v = fmaxf(fmaf(ssc[c], s, sbi[c]), 0.0f);
        }
        out[(((size_t)(b*CCD + c))*TTD + t)*PPD + p0 + pl] = v;
    }
}

// ---------------- launch ----------------
extern "C" void kernel_launch(void* const* d_in, const int* in_sizes, int n_in,
                              void* d_out, int out_size) {
    const float* pts   = (const float*)d_in[0];
    const float* W     = (const float*)d_in[1];
    const float* gamma = (const float*)d_in[2];
    const float* beta  = (const float*)d_in[3];
    float* out = (float*)d_out;
    int n = in_sizes[0] / 6;

    void *pp;
    cudaGetSymbolAddress(&pp, g_pil);
    cudaMemsetAsync(pp, 0, sizeof(float4)*(NSEG + ACC_PAD));   // stats + moments in one shot

    int nb = (n + 255) / 256;
    pass1<<<nb, 256>>>(pts, n);
    zero_multi<<<(NSEG + 255)/256, 256>>>(NSEG);
    pass23<<<296, 256>>>(pts, n, W);
    finalize_bn<<<1, 64>>>(W, gamma, beta);
    dim3 tg(PPD/64, BBD*TTD);
    transpose_k<<<tg, 256>>>(out);
}

// round 12
// speedup vs baseline: 1.2918x; 1.0612x over previous
#include <cuda_runtime.h>
#include <cstdint>

#define GXD 512
#define GYD 512
#define BBD 2
#define TTD 5
#define CCD 64
#define NSEG (BBD*TTD*GYD*GXD)   /* 2,621,440 */
#define PPD  (GYD*GXD)           /* 262,144  */
#define ACC_PAD 32               /* 32 float4 = 512B tail for g_acc (56 doubles = 448B) */

// ---------------- scratch (static __device__ — no allocations) ----------------
// g_pil[i] = (count, sum_x, sum_y, sum_z); tail [NSEG..NSEG+ACC_PAD) holds g_acc doubles
__device__ __align__(16) float4       g_pil[NSEG + ACC_PAD];
__device__ __align__(16) unsigned int g_canvas[(size_t)NSEG*CCD]; // order-preserving keys of RAW scores
__device__ __align__(16) float        g_scale[CCD]; // gamma * rstd
__device__ __align__(16) float        g_bias2[CCD]; // beta - mu*scale

__device__ __forceinline__ double* acc_ptr() { return (double*)&g_pil[NSEG]; }

// ---------------- helpers ----------------
// XLA algebraic simplifier rewrites (x - pcr)/vox into (x - pcr) * (1/vox);
// 1/0.2f rounds to exactly 5.0f. Replicate: add.rn then mul.rn by 5.0f.
__device__ __forceinline__ bool compute_cell(const float* __restrict__ pt,
                                             int& seg, float& x, float& y, float& z,
                                             int& cx, int& cy) {
    float b = pt[0]; x = pt[1]; y = pt[2]; z = pt[3]; float t = pt[5];
    float cfx = __fmul_rn(__fadd_rn(x, 51.2f), 5.0f);
    float cfy = __fmul_rn(__fadd_rn(y, 51.2f), 5.0f);
    bool valid = (cfx >= 0.f) && (cfx < (float)GXD) && (cfy >= 0.f) && (cfy < (float)GYD);
    cx = (int)cfx; cx = cx < 0 ? 0 : (cx > GXD-1 ? GXD-1 : cx);
    cy = (int)cfy; cy = cy < 0 ? 0 : (cy > GYD-1 ? GYD-1 : cy);
    int bi = (int)b, ti = (int)t;
    seg = ((bi*TTD + ti)*GYD + cy)*GXD + cx;
    return valid;
}

__device__ __forceinline__ float warpsum(float v) {
    v += __shfl_down_sync(0xffffffffu, v, 16);
    v += __shfl_down_sync(0xffffffffu, v, 8);
    v += __shfl_down_sync(0xffffffffu, v, 4);
    v += __shfl_down_sync(0xffffffffu, v, 2);
    v += __shfl_down_sync(0xffffffffu, v, 1);
    return v;
}

// one float4 gather replaces 4 scattered scalar loads
__device__ __forceinline__ float build_feats(float* f, float x, float y, float z,
                                             float inten, int seg, int cx, int cy) {
    float4 p = g_pil[seg];
    float cnt = p.x;
    float d   = fmaxf(cnt, 1.0f);
    float mx  = __fdiv_rn(p.y, d);
    float my  = __fdiv_rn(p.z, d);
    float mz  = __fdiv_rn(p.w, d);
    float cenx = __fadd_rn(__fadd_rn(__fmul_rn((float)cx, 0.2f), 0.1f), -51.2f);
    float ceny = __fadd_rn(__fadd_rn(__fmul_rn((float)cy, 0.2f), 0.1f), -51.2f);
    f[0] = x; f[1] = y; f[2] = z; f[3] = inten;
    f[4] = x - mx; f[5] = y - my; f[6] = z - mz;
    f[7] = x - cenx; f[8] = y - ceny;
    return cnt;
}

// order-preserving float<->uint key (works for negative raw scores)
__device__ __forceinline__ unsigned enc_key(float f) {
    int i = __float_as_int(f);
    return (i >= 0) ? ((unsigned)i | 0x80000000u) : ~(unsigned)i;
}
__device__ __forceinline__ float dec_key(unsigned k) {
    int i = (k & 0x80000000u) ? (int)(k & 0x7FFFFFFFu) : (int)(~k);
    return __int_as_float(i);
}

// ------- dummy: shifts the fixed ncu capture slot onto pass23 -----------------
__global__ void dummy_k() {}

// ---------------- pass 1: per-pillar count + xyz sums ----------------
__global__ void pass1(const float* __restrict__ pts, int n) {
    int i = blockIdx.x*blockDim.x + threadIdx.x;
    bool valid = false; int seg = 0, cx, cy; float x = 0.f, y = 0.f, z = 0.f;
    if (i < n) valid = compute_cell(pts + (size_t)i*6, seg, x, y, z, cx, cy);
    if (valid) {
        float* p = (float*)&g_pil[seg];   // 4 atomics into one 16B span (same line)
        atomicAdd(p + 0, 1.0f);
        atomicAdd(p + 1, x);
        atomicAdd(p + 2, y);
        atomicAdd(p + 3, z);
    }
}

// -------- zero canvas rows only where cnt >= 2 (atomicMax baseline = key 0) ---
__global__ void zero_multi(int nseg) {
    int i = blockIdx.x*blockDim.x + threadIdx.x;
    if (i >= nseg) return;
    if (g_pil[i].x >= 2.0f) {
        uint4* p = (uint4*)&g_canvas[(size_t)i*CCD];
        uint4 zz = make_uint4(0u,0u,0u,0u);
        #pragma unroll
        for (int k = 0; k < 16; k++) p[k] = zz;
    }
}

// ------- fused pass: moments+nvalid (register-accumulated) + matvec max -------
__global__ void __launch_bounds__(256) pass23(const float* __restrict__ pts, int n,
                                              const float* __restrict__ W) {
    __shared__ float4 sW[9*16];   // raw W [r][c4]
    __shared__ double sacc[55];
    int tid = threadIdx.x;
    if (tid < 144) sW[tid] = ((const float4*)W)[tid];
    if (tid < 55)  sacc[tid] = 0.0;
    __syncthreads();

    float m[55];
    #pragma unroll
    for (int k = 0; k < 55; k++) m[k] = 0.f;

    int stride = gridDim.x * blockDim.x;
    for (int i = blockIdx.x*blockDim.x + tid; i < n; i += stride) {
        int seg, cx, cy; float x, y, z;
        bool valid = compute_cell(pts + (size_t)i*6, seg, x, y, z, cx, cy);
        if (!valid) continue;
        float inten = pts[(size_t)i*6 + 4];
        float f[9];
        float cnt = build_feats(f, x, y, z, inten, seg, cx, cy);

        // moments + valid count in registers
        int k = 0;
        #pragma unroll
        for (int a = 0; a < 9; a++, k++) m[k] += f[a];
        #pragma unroll
        for (int a = 0; a < 9; a++)
            #pragma unroll
            for (int b2 = a; b2 < 9; b2++, k++) m[k] = fmaf(f[a], f[b2], m[k]);
        m[54] += 1.0f;

        // raw matvec + scatter-max (keys)
        unsigned* base = &g_canvas[(size_t)seg * CCD];
        bool single = (cnt == 1.0f);
        #pragma unroll
        for (int c4 = 0; c4 < 16; c4++) {
            float4 acc = make_float4(0.f,0.f,0.f,0.f);
            #pragma unroll
            for (int r = 0; r < 9; r++) {
                float4 wv = sW[r*16 + c4];
                acc.x = fmaf(f[r], wv.x, acc.x);
                acc.y = fmaf(f[r], wv.y, acc.y);
                acc.z = fmaf(f[r], wv.z, acc.z);
                acc.w = fmaf(f[r], wv.w, acc.w);
            }
            unsigned kx = enc_key(acc.x), ky = enc_key(acc.y);
            unsigned kz = enc_key(acc.z), kw = enc_key(acc.w);
            if (single) {
                ((uint4*)base)[c4] = make_uint4(kx, ky, kz, kw);
            } else {
                atomicMax(base + c4*4 + 0, kx);
                atomicMax(base + c4*4 + 1, ky);
                atomicMax(base + c4*4 + 2, kz);
                atomicMax(base + c4*4 + 3, kw);
            }
        }
    }

    // block-level reduction (55 accumulators)
    bool lane0 = ((tid & 31) == 0);
    #pragma unroll
    for (int k = 0; k < 55; k++) {
        float v = warpsum(m[k]);
        if (lane0 && v != 0.f) atomicAdd(&sacc[k], (double)v);
    }
    __syncthreads();
    if (tid < 55) {
        double v = sacc[tid];
        if (v != 0.0) atomicAdd(&acc_ptr()[tid], v);
    }
}

// ---------------- finalize: BN scale/bias from moments ----------------
__global__ void finalize_bn(const float* __restrict__ W,
                            const float* __restrict__ gamma,
                            const float* __restrict__ beta) {
    int c = threadIdx.x;   // 64 threads
    const double* ga = acc_ptr();
    double nv = ga[54]; if (nv < 1.0) nv = 1.0;
    float w[9];
    #pragma unroll
    for (int r = 0; r < 9; r++) w[r] = W[r*CCD + c];
    double mu = 0.0;
    #pragma unroll
    for (int r = 0; r < 9; r++) mu += ga[r] * (double)w[r];
    mu /= nv;
    double ex2 = 0.0; int k = 9;
    #pragma unroll
    for (int a = 0; a < 9; a++) {
        #pragma unroll
        for (int b2 = a; b2 < 9; b2++, k++) {
            double contrib = ga[k] * (double)w[a] * (double)w[b2];
            if (a != b2) contrib *= 2.0;
            ex2 += contrib;
        }
    }
    ex2 /= nv;
    double var = ex2 - mu*mu;
    float rstd = rsqrtf((float)var + 1e-3f);
    float sc = gamma[c] * rstd;
    g_scale[c] = sc;
    g_bias2[c] = beta[c] - (float)mu * sc;
}

// --- transpose + BN+relu: [B,T,GY,GX,C] -> [B,C,T,GY,GX], skip empty reads ----
__global__ void transpose_k(float* __restrict__ out) {
    __shared__ unsigned tile[64][65];
    __shared__ float scnt[64];
    __shared__ float ssc[CCD], sbi[CCD];
    int bt = blockIdx.y;                 // 0..9
    int p0 = blockIdx.x * 64;            // pillar base within one (b,t) plane
    int b  = bt / TTD, t = bt % TTD;
    int tid = threadIdx.x;               // 256 threads

    if (tid < 64)        scnt[tid] = g_pil[(size_t)bt * PPD + p0 + tid].x;
    else if (tid < 128)  ssc[tid-64] = g_scale[tid-64];
    else if (tid < 192)  sbi[tid-128] = g_bias2[tid-128];
    __syncthreads();

    const unsigned* src = g_canvas + ((size_t)bt * PPD + p0) * CCD;
    #pragma unroll
    for (int it = 0; it < 4; it++) {
        int row = it*16 + (tid >> 4);
        int v   = tid & 15;
        if (scnt[row] > 0.0f) {          // skip 256B read for empty pillars
            uint4 d = *(const uint4*)(src + (size_t)row*CCD + v*4);
            tile[row][v*4+0] = d.x; tile[row][v*4+1] = d.y;
            tile[row][v*4+2] = d.z; tile[row][v*4+3] = d.w;
        }
    }
    __syncthreads();
    #pragma unroll
    for (int it = 0; it < 16; it++) {
        int c  = it*4 + (tid >> 6);
        int pl = tid & 63;
        float v = 0.0f;
        if (scnt[pl] > 0.0f) {
            float s = dec_key(tile[pl][c]);
            v = fmaxf(fmaf(ssc[c], s, sbi[c]), 0.0f);
        }
        out[(((size_t)(b*CCD + c))*TTD + t)*PPD + p0 + pl] = v;
    }
}

// ---------------- launch ----------------
extern "C" void kernel_launch(void* const* d_in, const int* in_sizes, int n_in,
                              void* d_out, int out_size) {
    const float* pts   = (const float*)d_in[0];
    const float* W     = (const float*)d_in[1];
    const float* gamma = (const float*)d_in[2];
    const float* beta  = (const float*)d_in[3];
    float* out = (float*)d_out;
    int n = in_sizes[0] / 6;

    void *pp;
    cudaGetSymbolAddress(&pp, g_pil);
    cudaMemsetAsync(pp, 0, sizeof(float4)*(NSEG + ACC_PAD));   // stats + moments in one shot

    int nb = (n + 255) / 256;
    dummy_k<<<1, 32>>>();                 // shifts ncu capture slot onto pass23
    pass1<<<nb, 256>>>(pts, n);
    zero_multi<<<(NSEG + 255)/256, 256>>>(NSEG);
    pass23<<<296, 256>>>(pts, n, W);
    finalize_bn<<<1, 64>>>(W, gamma, beta);
    dim3 tg(PPD/64, BBD*TTD);
    transpose_k<<<tg, 256>>>(out);
}

// round 13
// speedup vs baseline: 1.3944x; 1.0794x over previous
#include <cuda_runtime.h>
#include <cstdint>

#define GXD 512
#define GYD 512
#define BBD 2
#define TTD 5
#define CCD 64
#define NSEG (BBD*TTD*GYD*GXD)   /* 2,621,440 */
#define PPD  (GYD*GXD)           /* 262,144  */
#define ACC_PAD 32               /* tail for g_acc (56 doubles) */

// ---------------- scratch (static __device__ — no allocations) ----------------
__device__ __align__(16) float4       g_pil[NSEG + ACC_PAD];
__device__ __align__(16) unsigned int g_canvas[(size_t)NSEG*CCD];
__device__ __align__(16) float        g_scale[CCD];
__device__ __align__(16) float        g_bias2[CCD];

__device__ __forceinline__ double* acc_ptr() { return (double*)&g_pil[NSEG]; }

// ---------------- helpers ----------------
// XLA rewrites (x - pcr)/vox -> (x - pcr) * (1/vox); 1/0.2f == 5.0f exactly.
__device__ __forceinline__ bool cell_from_xy(float x, float y, float b, float t,
                                             int& seg, int& cx, int& cy) {
    float cfx = __fmul_rn(__fadd_rn(x, 51.2f), 5.0f);
    float cfy = __fmul_rn(__fadd_rn(y, 51.2f), 5.0f);
    bool valid = (cfx >= 0.f) && (cfx < (float)GXD) && (cfy >= 0.f) && (cfy < (float)GYD);
    cx = (int)cfx; cx = cx < 0 ? 0 : (cx > GXD-1 ? GXD-1 : cx);
    cy = (int)cfy; cy = cy < 0 ? 0 : (cy > GYD-1 ? GYD-1 : cy);
    int bi = (int)b, ti = (int)t;
    seg = ((bi*TTD + ti)*GYD + cy)*GXD + cx;
    return valid;
}

__device__ __forceinline__ float warpsum(float v) {
    v += __shfl_down_sync(0xffffffffu, v, 16);
    v += __shfl_down_sync(0xffffffffu, v, 8);
    v += __shfl_down_sync(0xffffffffu, v, 4);
    v += __shfl_down_sync(0xffffffffu, v, 2);
    v += __shfl_down_sync(0xffffffffu, v, 1);
    return v;
}

__device__ __forceinline__ void feats_from(float* f, float x, float y, float z,
                                           float inten, float4 p, int cx, int cy) {
    float d   = fmaxf(p.x, 1.0f);
    float mx  = __fdiv_rn(p.y, d);
    float my  = __fdiv_rn(p.z, d);
    float mz  = __fdiv_rn(p.w, d);
    float cenx = __fadd_rn(__fadd_rn(__fmul_rn((float)cx, 0.2f), 0.1f), -51.2f);
    float ceny = __fadd_rn(__fadd_rn(__fmul_rn((float)cy, 0.2f), 0.1f), -51.2f);
    f[0] = x; f[1] = y; f[2] = z; f[3] = inten;
    f[4] = x - mx; f[5] = y - my; f[6] = z - mz;
    f[7] = x - cenx; f[8] = y - ceny;
}

// order-preserving float<->uint key
__device__ __forceinline__ unsigned enc_key(float f) {
    int i = __float_as_int(f);
    return (i >= 0) ? ((unsigned)i | 0x80000000u) : ~(unsigned)i;
}
__device__ __forceinline__ float dec_key(unsigned k) {
    int i = (k & 0x80000000u) ? (int)(k & 0x7FFFFFFFu) : (int)(~k);
    return __int_as_float(i);
}

// ---------------- pass 1: per-pillar count + xyz sums ----------------
__global__ void pass1(const float* __restrict__ pts, int n) {
    int i = blockIdx.x*blockDim.x + threadIdx.x;
    if (i >= n) return;
    const float* pt = pts + (size_t)i*6;
    float b = pt[0], x = pt[1], y = pt[2], z = pt[3], t = pt[5];
    int seg, cx, cy;
    if (cell_from_xy(x, y, b, t, seg, cx, cy)) {
        float* p = (float*)&g_pil[seg];
        atomicAdd(p + 0, 1.0f);
        atomicAdd(p + 1, x);
        atomicAdd(p + 2, y);
        atomicAdd(p + 3, z);
    }
}

// -------- zero canvas rows only where cnt >= 2 ----------
__global__ void zero_multi(int nseg) {
    int i = blockIdx.x*blockDim.x + threadIdx.x;
    if (i >= nseg) return;
    if (g_pil[i].x >= 2.0f) {
        uint4* p = (uint4*)&g_canvas[(size_t)i*CCD];
        uint4 zz = make_uint4(0u,0u,0u,0u);
        #pragma unroll
        for (int k = 0; k < 16; k++) p[k] = zz;
    }
}

// ---------------- momk: moments + nvalid, 2 points/iter, no stores ------------
__global__ void __launch_bounds__(256) momk(const float* __restrict__ pts, int n) {
    __shared__ double sacc[55];
    int tid = threadIdx.x;
    if (tid < 55) sacc[tid] = 0.0;
    __syncthreads();

    float m[55];
    #pragma unroll
    for (int k = 0; k < 55; k++) m[k] = 0.f;

    int step = gridDim.x * blockDim.x;
    for (int i = blockIdx.x*blockDim.x + tid; i < n; i += 2*step) {
        int i1 = i + step;
        bool has1 = (i1 < n);
        const float* p0 = pts + (size_t)i*6;
        const float* p1 = pts + (size_t)(has1 ? i1 : i)*6;
        float b0=p0[0], x0=p0[1], y0=p0[2], z0=p0[3], w0=p0[4], t0=p0[5];
        float b1=p1[0], x1=p1[1], y1=p1[2], z1=p1[3], w1=p1[4], t1=p1[5];
        int seg0, cx0, cy0, seg1, cx1, cy1;
        bool v0 = cell_from_xy(x0, y0, b0, t0, seg0, cx0, cy0);
        bool v1 = has1 && cell_from_xy(x1, y1, b1, t1, seg1, cx1, cy1);
        float4 q0 = make_float4(0,0,0,0), q1 = make_float4(0,0,0,0);
        if (v0) q0 = g_pil[seg0];          // both gathers in flight together
        if (v1) q1 = g_pil[seg1];

        if (v0) {
            float f[9];
            feats_from(f, x0, y0, z0, w0, q0, cx0, cy0);
            int k = 0;
            #pragma unroll
            for (int a = 0; a < 9; a++, k++) m[k] += f[a];
            #pragma unroll
            for (int a = 0; a < 9; a++)
                #pragma unroll
                for (int b2 = a; b2 < 9; b2++, k++) m[k] = fmaf(f[a], f[b2], m[k]);
            m[54] += 1.0f;
        }
        if (v1) {
            float f[9];
            feats_from(f, x1, y1, z1, w1, q1, cx1, cy1);
            int k = 0;
            #pragma unroll
            for (int a = 0; a < 9; a++, k++) m[k] += f[a];
            #pragma unroll
            for (int a = 0; a < 9; a++)
                #pragma unroll
                for (int b2 = a; b2 < 9; b2++, k++) m[k] = fmaf(f[a], f[b2], m[k]);
            m[54] += 1.0f;
        }
    }

    bool lane0 = ((tid & 31) == 0);
    #pragma unroll
    for (int k = 0; k < 55; k++) {
        float v = warpsum(m[k]);
        if (lane0 && v != 0.f) atomicAdd(&sacc[k], (double)v);
    }
    __syncthreads();
    if (tid < 55) {
        double v = sacc[tid];
        if (v != 0.0) atomicAdd(&acc_ptr()[tid], v);
    }
}

// ---------------- scatk: matvec + scatter-max, 1 point/thread, high occ -------
__global__ void __launch_bounds__(256, 4) scatk(const float* __restrict__ pts, int n,
                                                const float* __restrict__ W) {
    __shared__ float4 sW[9*16];
    int tid = threadIdx.x;
    if (tid < 144) sW[tid] = ((const float4*)W)[tid];
    __syncthreads();

    int i = blockIdx.x*blockDim.x + tid;
    if (i >= n) return;
    const float* pt = pts + (size_t)i*6;
    float b = pt[0], x = pt[1], y = pt[2], z = pt[3], inten = pt[4], t = pt[5];
    int seg, cx, cy;
    if (!cell_from_xy(x, y, b, t, seg, cx, cy)) return;
    float4 q = g_pil[seg];
    float f[9];
    feats_from(f, x, y, z, inten, q, cx, cy);

    unsigned* base = &g_canvas[(size_t)seg * CCD];
    bool single = (q.x == 1.0f);
    #pragma unroll
    for (int c4 = 0; c4 < 16; c4++) {
        float4 acc = make_float4(0.f,0.f,0.f,0.f);
        #pragma unroll
        for (int r = 0; r < 9; r++) {
            float4 wv = sW[r*16 + c4];
            acc.x = fmaf(f[r], wv.x, acc.x);
            acc.y = fmaf(f[r], wv.y, acc.y);
            acc.z = fmaf(f[r], wv.z, acc.z);
            acc.w = fmaf(f[r], wv.w, acc.w);
        }
        unsigned kx = enc_key(acc.x), ky = enc_key(acc.y);
        unsigned kz = enc_key(acc.z), kw = enc_key(acc.w);
        if (single) {
            ((uint4*)base)[c4] = make_uint4(kx, ky, kz, kw);
        } else {
            atomicMax(base + c4*4 + 0, kx);
            atomicMax(base + c4*4 + 1, ky);
            atomicMax(base + c4*4 + 2, kz);
            atomicMax(base + c4*4 + 3, kw);
        }
    }
}

// ---------------- finalize: BN scale/bias from moments ----------------
__global__ void finalize_bn(const float* __restrict__ W,
                            const float* __restrict__ gamma,
                            const float* __restrict__ beta) {
    int c = threadIdx.x;   // 64 threads
    const double* ga = acc_ptr();
    double nv = ga[54]; if (nv < 1.0) nv = 1.0;
    float w[9];
    #pragma unroll
    for (int r = 0; r < 9; r++) w[r] = W[r*CCD + c];
    double mu = 0.0;
    #pragma unroll
    for (int r = 0; r < 9; r++) mu += ga[r] * (double)w[r];
    mu /= nv;
    double ex2 = 0.0; int k = 9;
    #pragma unroll
    for (int a = 0; a < 9; a++) {
        #pragma unroll
        for (int b2 = a; b2 < 9; b2++, k++) {
            double contrib = ga[k] * (double)w[a] * (double)w[b2];
            if (a != b2) contrib *= 2.0;
            ex2 += contrib;
        }
    }
    ex2 /= nv;
    double var = ex2 - mu*mu;
    float rstd = rsqrtf((float)var + 1e-3f);
    float sc = gamma[c] * rstd;
    g_scale[c] = sc;
    g_bias2[c] = beta[c] - (float)mu * sc;
}

// --- transpose + BN+relu: [B,T,GY,GX,C] -> [B,C,T,GY,GX] ----------------------
__global__ void transpose_k(float* __restrict__ out) {
    __shared__ unsigned tile[64][65];
    __shared__ float scnt[64];
    __shared__ float ssc[CCD], sbi[CCD];
    int bt = blockIdx.y;
    int p0 = blockIdx.x * 64;
    int b  = bt / TTD, t = bt % TTD;
    int tid = threadIdx.x;

    if (tid < 64)        scnt[tid] = g_pil[(size_t)bt * PPD + p0 + tid].x;
    else if (tid < 128)  ssc[tid-64] = g_scale[tid-64];
    else if (tid < 192)  sbi[tid-128] = g_bias2[tid-128];
    __syncthreads();

    const unsigned* src = g_canvas + ((size_t)bt * PPD + p0) * CCD;
    #pragma unroll
    for (int it = 0; it < 4; it++) {
        int row = it*16 + (tid >> 4);
        int v   = tid & 15;
        if (scnt[row] > 0.0f) {
            uint4 d = *(const uint4*)(src + (size_t)row*CCD + v*4);
            tile[row][v*4+0] = d.x; tile[row][v*4+1] = d.y;
            tile[row][v*4+2] = d.z; tile[row][v*4+3] = d.w;
        }
    }
    __syncthreads();
    #pragma unroll
    for (int it = 0; it < 16; it++) {
        int c  = it*4 + (tid >> 6);
        int pl = tid & 63;
        float v = 0.0f;
        if (scnt[pl] > 0.0f) {
            float s = dec_key(tile[pl][c]);
            v = fmaxf(fmaf(ssc[c], s, sbi[c]), 0.0f);
        }
        out[(((size_t)(b*CCD + c))*TTD + t)*PPD + p0 + pl] = v;
    }
}

// ---------------- launch ----------------
extern "C" void kernel_launch(void* const* d_in, const int* in_sizes, int n_in,
                              void* d_out, int out_size) {
    const float* pts   = (const float*)d_in[0];
    const float* W     = (const float*)d_in[1];
    const float* gamma = (const float*)d_in[2];
    const float* beta  = (const float*)d_in[3];
    float* out = (float*)d_out;
    int n = in_sizes[0] / 6;

    void *pp;
    cudaGetSymbolAddress(&pp, g_pil);
    cudaMemsetAsync(pp, 0, sizeof(float4)*(NSEG + ACC_PAD));

    int nb = (n + 255) / 256;
    pass1<<<nb, 256>>>(pts, n);
    zero_multi<<<(NSEG + 255)/256, 256>>>(NSEG);
    momk<<<296, 256>>>(pts, n);
    scatk<<<nb, 256>>>(pts, n, W);      // 4th kernel -> ncu capture slot
    finalize_bn<<<1, 64>>>(W, gamma, beta);
    dim3 tg(PPD/64, BBD*TTD);
    transpose_k<<<tg, 256>>>(out);
}